// round 3
// baseline (speedup 1.0000x reference)
#include <cuda_runtime.h>
#include <cstdint>

#define N_NODES   100000
#define N_NODES_P 100032   // padded to multiple of 64 (GEMM tile)
#define CH        256      // in == out channels

// ---------------- scratch (static __device__ globals; no allocation) -------
__device__ float g_acc[(size_t)N_NODES_P * CH];  // ~102.4 MB
__device__ float g_deg[N_NODES_P];

// ---------------- helpers --------------------------------------------------
__device__ __forceinline__ void red_add_v4(float4* addr, float4 v) {
#if __CUDA_ARCH__ >= 900
    asm volatile("red.global.add.v4.f32 [%0], {%1, %2, %3, %4};"
                 :: "l"(addr), "f"(v.x), "f"(v.y), "f"(v.z), "f"(v.w)
                 : "memory");
#else
    atomicAdd(&addr->x, v.x); atomicAdd(&addr->y, v.y);
    atomicAdd(&addr->z, v.z); atomicAdd(&addr->w, v.w);
#endif
}

// ---------------- kernel 1: zero scratch -----------------------------------
__global__ void zero_kernel() {
    const size_t n4 = (size_t)N_NODES_P * CH / 4;
    float4 z = make_float4(0.f, 0.f, 0.f, 0.f);
    for (size_t i = (size_t)blockIdx.x * blockDim.x + threadIdx.x; i < n4;
         i += (size_t)gridDim.x * blockDim.x)
        reinterpret_cast<float4*>(g_acc)[i] = z;
    for (int i = blockIdx.x * blockDim.x + threadIdx.x; i < N_NODES_P;
         i += gridDim.x * blockDim.x)
        g_deg[i] = 0.f;
}

// ---------------- kernel 2: edge scatter (acc[dst] += x[src], deg[dst]++) --
// One warp per edge: lane handles float4 columns {lane, lane+32} of 64.
// NOTE: indices are int32 (JAX downgrades int64 without x64 mode).
__global__ __launch_bounds__(256) void scatter_kernel(
    const float* __restrict__ x,
    const int* __restrict__ src,
    const int* __restrict__ dst,
    int n_edges)
{
    const int lane    = threadIdx.x & 31;
    const int warp    = (blockIdx.x * blockDim.x + threadIdx.x) >> 5;
    const int n_warps = (gridDim.x * blockDim.x) >> 5;

    for (int e = warp; e < n_edges; e += n_warps) {
        const int s = src[e];   // broadcast load within warp
        const int d = dst[e];
        const float4* xr = reinterpret_cast<const float4*>(x + (size_t)s * CH);
        float4* ar       = reinterpret_cast<float4*>(g_acc + (size_t)d * CH);
        float4 v0 = __ldg(xr + lane);
        float4 v1 = __ldg(xr + lane + 32);
        red_add_v4(ar + lane,      v0);
        red_add_v4(ar + lane + 32, v1);
        if (lane == 0) atomicAdd(&g_deg[d], 1.0f);
    }
}

// ---------------- kernel 3: out = (acc @ W + cnt*b) / max(cnt,1) -----------
// Tile: 64 rows x 256 cols per block, 256 threads.
// Thread (tx in [0,64): float4 column, ty in [0,4): 16 rows each).
__global__ __launch_bounds__(256) void gemm_kernel(
    const float* __restrict__ W,      // [256,256] row-major: W[k*256 + n]
    const float* __restrict__ bias,   // [256]
    float* __restrict__ out,          // [N_NODES,256]
    int n_nodes)
{
    __shared__ float  xs[64 * 36];      // 64 rows x 32 k (stride 36 pad)
    __shared__ float4 ws[32 * 64];      // 32 k x 64 float4-cols

    const int tid  = threadIdx.x;
    const int tx   = tid & 63;
    const int ty   = tid >> 6;
    const int row0 = blockIdx.x * 64;

    float4 acc[16];
#pragma unroll
    for (int r = 0; r < 16; r++) acc[r] = make_float4(0.f, 0.f, 0.f, 0.f);

    for (int kk = 0; kk < CH; kk += 32) {
        // load x tile: 64 rows x 32 floats = 512 float4; 2 per thread
#pragma unroll
        for (int i = 0; i < 2; i++) {
            int id = tid + i * 256;
            int r  = id >> 3;
            int c4 = id & 7;
            float4 v = *reinterpret_cast<const float4*>(
                g_acc + (size_t)(row0 + r) * CH + kk + c4 * 4);
            xs[r * 36 + c4 * 4 + 0] = v.x;
            xs[r * 36 + c4 * 4 + 1] = v.y;
            xs[r * 36 + c4 * 4 + 2] = v.z;
            xs[r * 36 + c4 * 4 + 3] = v.w;
        }
        // load W tile: 32 k x 256 floats = 2048 float4; 8 per thread
#pragma unroll
        for (int i = 0; i < 8; i++) {
            int id = tid + i * 256;
            int k  = id >> 6;
            int n4 = id & 63;
            ws[k * 64 + n4] = *reinterpret_cast<const float4*>(
                W + (size_t)(kk + k) * CH + n4 * 4);
        }
        __syncthreads();

#pragma unroll
        for (int k = 0; k < 32; k++) {
            float4 w = ws[k * 64 + tx];
#pragma unroll
            for (int r = 0; r < 16; r++) {
                float a = xs[(ty * 16 + r) * 36 + k];   // warp-broadcast
                acc[r].x += a * w.x;
                acc[r].y += a * w.y;
                acc[r].z += a * w.z;
                acc[r].w += a * w.w;
            }
        }
        __syncthreads();
    }

    float4 b4 = reinterpret_cast<const float4*>(bias)[tx];
#pragma unroll
    for (int r = 0; r < 16; r++) {
        int row = row0 + ty * 16 + r;
        if (row < n_nodes) {
            float cnt   = g_deg[row];
            float scale = 1.0f / fmaxf(cnt, 1.0f);
            float4 o;
            o.x = (acc[r].x + cnt * b4.x) * scale;
            o.y = (acc[r].y + cnt * b4.y) * scale;
            o.z = (acc[r].z + cnt * b4.z) * scale;
            o.w = (acc[r].w + cnt * b4.w) * scale;
            reinterpret_cast<float4*>(out)[(size_t)row * (CH / 4) + tx] = o;
        }
    }
}

// ---------------- launch ---------------------------------------------------
extern "C" void kernel_launch(void* const* d_in, const int* in_sizes, int n_in,
                              void* d_out, int out_size)
{
    const float* x    = (const float*)d_in[0];
    const int*   src  = (const int*)d_in[1];
    const int*   dst  = (const int*)d_in[2];
    const float* W    = (const float*)d_in[3];
    const float* bias = (const float*)d_in[4];
    float*       out  = (float*)d_out;

    const int n_nodes = in_sizes[0] / CH;
    const int n_edges = in_sizes[1];

    zero_kernel<<<1024, 256>>>();
    scatter_kernel<<<2048, 256>>>(x, src, dst, n_edges);
    gemm_kernel<<<(n_nodes + 63) / 64, 256>>>(W, bias, out, n_nodes);
}

// round 6
// speedup vs baseline: 2.3926x; 2.3926x over previous
#include <cuda_runtime.h>
#include <cstdint>

#define N_NODES   100000
#define N_NODES_P 100032     // padded to multiple of 64 (GEMM tile)
#define N_EDGES_MAX 3200000
#define CH        256        // in == out channels

// ---------------- scratch (static __device__ globals; no allocation) -------
__device__ float g_acc[(size_t)N_NODES_P * CH];   // ~102.4 MB
__device__ int   g_deg[N_NODES_P];
__device__ int   g_start[N_NODES_P];
__device__ int   g_cursor[N_NODES_P];
__device__ int   g_sorted_src[N_EDGES_MAX];
__device__ int   g_total;

// ---------------- kernel A: zero degree counters ---------------------------
__global__ void zero_deg_kernel() {
    int i = blockIdx.x * blockDim.x + threadIdx.x;
    if (i < N_NODES_P) g_deg[i] = 0;
    if (i == 0) g_total = 0;
}

// ---------------- kernel B: degree histogram -------------------------------
__global__ __launch_bounds__(256) void hist_kernel(
    const int* __restrict__ dst, int n_edges)
{
    for (int e = blockIdx.x * blockDim.x + threadIdx.x; e < n_edges;
         e += gridDim.x * blockDim.x)
        atomicAdd(&g_deg[dst[e]], 1);     // no return use -> RED
}

// ---------------- kernel C: per-node bucket base (warp-aggregated) ---------
// Each warp scans 32 degrees, grabs one chunk of edge space via a single
// atomicAdd on g_total, and distributes per-node start offsets. The
// resulting buckets are an arbitrary-order but valid partition of the
// edge index space — aggregation only needs per-node contiguity.
__global__ __launch_bounds__(256) void offsets_kernel(int n_nodes) {
    int i    = blockIdx.x * blockDim.x + threadIdx.x;
    int lane = threadIdx.x & 31;
    int d    = (i < n_nodes) ? g_deg[i] : 0;

    int incl = d;
#pragma unroll
    for (int o = 1; o < 32; o <<= 1) {
        int t = __shfl_up_sync(0xffffffffu, incl, o);
        if (lane >= o) incl += t;
    }
    int total = __shfl_sync(0xffffffffu, incl, 31);
    int base  = 0;
    if (lane == 31) base = atomicAdd(&g_total, total);
    base = __shfl_sync(0xffffffffu, base, 31);

    if (i < n_nodes) {
        int st = base + incl - d;
        g_start[i]  = st;
        g_cursor[i] = st;
    }
}

// ---------------- kernel D: bucket edges by dst ----------------------------
__global__ __launch_bounds__(256) void bucket_kernel(
    const int* __restrict__ src, const int* __restrict__ dst, int n_edges)
{
    for (int e = blockIdx.x * blockDim.x + threadIdx.x; e < n_edges;
         e += gridDim.x * blockDim.x) {
        int d = dst[e];
        int s = src[e];                       // overlap load with ATOMG
        int pos = atomicAdd(&g_cursor[d], 1);
        g_sorted_src[pos] = s;
    }
}

// ---------------- kernel E: gather-aggregate (no atomics) ------------------
// One warp per dst node; lane holds float4 columns {lane, lane+32}.
// acc row written exactly once -> no zeroing of g_acc needed.
__global__ __launch_bounds__(256) void aggregate_kernel(
    const float* __restrict__ x, int n_nodes)
{
    const int warp = (blockIdx.x * blockDim.x + threadIdx.x) >> 5;
    const int lane = threadIdx.x & 31;
    if (warp >= n_nodes) return;

    const int beg = g_start[warp];
    const int cnt = g_deg[warp];

    float4 a0 = make_float4(0.f, 0.f, 0.f, 0.f);
    float4 a1 = make_float4(0.f, 0.f, 0.f, 0.f);

    for (int j0 = 0; j0 < cnt; j0 += 32) {
        int idx = 0;
        if (j0 + lane < cnt) idx = g_sorted_src[beg + j0 + lane];
        const int m = min(32, cnt - j0);
        for (int j = 0; j < m; j++) {
            int s = __shfl_sync(0xffffffffu, idx, j);
            const float4* xr = reinterpret_cast<const float4*>(x + (size_t)s * CH);
            float4 v0 = __ldg(xr + lane);
            float4 v1 = __ldg(xr + lane + 32);
            a0.x += v0.x; a0.y += v0.y; a0.z += v0.z; a0.w += v0.w;
            a1.x += v1.x; a1.y += v1.y; a1.z += v1.z; a1.w += v1.w;
        }
    }

    float4* ar = reinterpret_cast<float4*>(g_acc + (size_t)warp * CH);
    ar[lane]      = a0;
    ar[lane + 32] = a1;
}

// ---------------- kernel F: out = (acc @ W + deg*b) / max(deg,1) -----------
// Tile: 64 rows x 256 cols per block, 256 threads.
__global__ __launch_bounds__(256) void gemm_kernel(
    const float* __restrict__ W,      // [256,256] row-major: W[k*256 + n]
    const float* __restrict__ bias,   // [256]
    float* __restrict__ out,          // [N_NODES,256]
    int n_nodes)
{
    __shared__ float  xs[64 * 36];      // 64 rows x 32 k (stride 36 pad)
    __shared__ float4 ws[32 * 64];      // 32 k x 64 float4-cols

    const int tid  = threadIdx.x;
    const int tx   = tid & 63;
    const int ty   = tid >> 6;
    const int row0 = blockIdx.x * 64;

    float4 acc[16];
#pragma unroll
    for (int r = 0; r < 16; r++) acc[r] = make_float4(0.f, 0.f, 0.f, 0.f);

    for (int kk = 0; kk < CH; kk += 32) {
        // load x tile: 64 rows x 32 floats = 512 float4; 2 per thread
#pragma unroll
        for (int i = 0; i < 2; i++) {
            int id = tid + i * 256;
            int r  = id >> 3;
            int c4 = id & 7;
            float4 v = *reinterpret_cast<const float4*>(
                g_acc + (size_t)(row0 + r) * CH + kk + c4 * 4);
            xs[r * 36 + c4 * 4 + 0] = v.x;
            xs[r * 36 + c4 * 4 + 1] = v.y;
            xs[r * 36 + c4 * 4 + 2] = v.z;
            xs[r * 36 + c4 * 4 + 3] = v.w;
        }
        // load W tile: 32 k x 256 floats = 2048 float4; 8 per thread
#pragma unroll
        for (int i = 0; i < 8; i++) {
            int id = tid + i * 256;
            int k  = id >> 6;
            int n4 = id & 63;
            ws[k * 64 + n4] = *reinterpret_cast<const float4*>(
                W + (size_t)(kk + k) * CH + n4 * 4);
        }
        __syncthreads();

#pragma unroll
        for (int k = 0; k < 32; k += 4) {
            float4 w0 = ws[(k + 0) * 64 + tx];
            float4 w1 = ws[(k + 1) * 64 + tx];
            float4 w2 = ws[(k + 2) * 64 + tx];
            float4 w3 = ws[(k + 3) * 64 + tx];
#pragma unroll
            for (int r = 0; r < 16; r++) {
                // LDS.128: (ty*16+r)*36 + k is 16B aligned (36r+k ≡ 0 mod 4)
                float4 a = *reinterpret_cast<const float4*>(
                    &xs[(ty * 16 + r) * 36 + k]);
                acc[r].x += a.x * w0.x; acc[r].y += a.x * w0.y;
                acc[r].z += a.x * w0.z; acc[r].w += a.x * w0.w;
                acc[r].x += a.y * w1.x; acc[r].y += a.y * w1.y;
                acc[r].z += a.y * w1.z; acc[r].w += a.y * w1.w;
                acc[r].x += a.z * w2.x; acc[r].y += a.z * w2.y;
                acc[r].z += a.z * w2.z; acc[r].w += a.z * w2.w;
                acc[r].x += a.w * w3.x; acc[r].y += a.w * w3.y;
                acc[r].z += a.w * w3.z; acc[r].w += a.w * w3.w;
            }
        }
        __syncthreads();
    }

    float4 b4 = reinterpret_cast<const float4*>(bias)[tx];
#pragma unroll
    for (int r = 0; r < 16; r++) {
        int row = row0 + ty * 16 + r;
        if (row < n_nodes) {
            float cnt   = (float)g_deg[row];
            float scale = 1.0f / fmaxf(cnt, 1.0f);
            float4 o;
            o.x = (acc[r].x + cnt * b4.x) * scale;
            o.y = (acc[r].y + cnt * b4.y) * scale;
            o.z = (acc[r].z + cnt * b4.z) * scale;
            o.w = (acc[r].w + cnt * b4.w) * scale;
            reinterpret_cast<float4*>(out)[(size_t)row * (CH / 4) + tx] = o;
        }
    }
}

// ---------------- launch ---------------------------------------------------
extern "C" void kernel_launch(void* const* d_in, const int* in_sizes, int n_in,
                              void* d_out, int out_size)
{
    const float* x    = (const float*)d_in[0];
    const int*   src  = (const int*)d_in[1];
    const int*   dst  = (const int*)d_in[2];
    const float* W    = (const float*)d_in[3];
    const float* bias = (const float*)d_in[4];
    float*       out  = (float*)d_out;

    const int n_nodes = in_sizes[0] / CH;
    const int n_edges = in_sizes[1];

    zero_deg_kernel<<<(N_NODES_P + 255) / 256, 256>>>();
    hist_kernel<<<1184, 256>>>(dst, n_edges);
    offsets_kernel<<<(n_nodes + 255) / 256, 256>>>(n_nodes);
    bucket_kernel<<<1184, 256>>>(src, dst, n_edges);
    aggregate_kernel<<<(n_nodes * 32 + 255) / 256, 256>>>(x, n_nodes);
    gemm_kernel<<<(n_nodes + 63) / 64, 256>>>(W, bias, out, n_nodes);
}